// round 5
// baseline (speedup 1.0000x reference)
#include <cuda_runtime.h>
#include <math.h>

#define NN 10000
#define NE 160000

// ---------------- scratch (static device globals; no allocation) ----------------
__device__ float g_US[NE * 4];           // sorted unit vectors (float4 per CSR slot)
__device__ int   g_srcs[NE];             // sorted src node per CSR slot
__device__ int   g_cnt[NN];              // INVARIANT: zero at kernel_launch entry/exit
__device__ int   g_off[NN + 1];
__device__ int   g_cur[NN];
__device__ float g_H0[NN * 32];          // (N,C)
__device__ float g_H1[NN * 96];          // (N, d-major: d*32 + ch)
__device__ float g_H2[NN * 288];         // (N, d-major: d*32 + ch)
__device__ float g_ACC[NE * 96];         // per-CSR-slot acc (k index)
__device__ float g_accvec[96];           // layer-0 constant acc vector
__device__ float g_M[NN * 416];          // layer-1 messages

// ---------------- packed f32x2 helpers ----------------
__device__ __forceinline__ unsigned long long pack2(float x, float y) {
    unsigned long long r; asm("mov.b64 %0, {%1,%2};" : "=l"(r) : "f"(x), "f"(y)); return r;
}
__device__ __forceinline__ void unpack2(unsigned long long v, float& x, float& y) {
    asm("mov.b64 {%0,%1}, %2;" : "=f"(x), "=f"(y) : "l"(v));
}
__device__ __forceinline__ unsigned long long fma2(unsigned long long a, unsigned long long b,
                                                   unsigned long long c) {
    unsigned long long d;
    asm("fma.rn.f32x2 %0, %1, %2, %3;" : "=l"(d) : "l"(a), "l"(b), "l"(c));
    return d;
}

// ---------------- init: embed atoms, dst histogram, layer-0 accvec ----------------
// Requires g_cnt == 0 on entry (static init / re-zeroed by k_scan every call).
__global__ void k_init(const float* __restrict__ emb, const int* __restrict__ atoms,
                       const float* __restrict__ W_ab, const int* __restrict__ ei) {
    int t = blockIdx.x * 256 + threadIdx.x;
    if (t < NN * 32) g_H0[t] = emb[atoms[t >> 5] * 32 + (t & 31)];
    if (t < NE)      atomicAdd(&g_cnt[ei[NE + t]], 1);
    if (t < 96) {
        int c = t >> 5, j = t & 31;
        const float* wp = W_ab + (c * 3) * 1024 + j * 32;
        float s = 0.f;
#pragma unroll
        for (int k = 0; k < 32; k++) s += wp[k] * emb[k];
        g_accvec[t] = s;
    }
}

// ---------------- single-block exclusive scan; re-zeroes g_cnt ----------------
__global__ void k_scan() {
    __shared__ int sh[1024];
    int t = threadIdx.x;
    const int PER = 10;
    int base = t * PER;
    int loc[PER];
    int s = 0;
#pragma unroll
    for (int i = 0; i < PER; i++) {
        int idx = base + i;
        int v = (idx < NN) ? g_cnt[idx] : 0;
        if (idx < NN) g_cnt[idx] = 0;          // restore invariant for next call
        loc[i] = s;
        s += v;
    }
    sh[t] = s;
    __syncthreads();
    for (int off = 1; off < 1024; off <<= 1) {
        int v = (t >= off) ? sh[t - off] : 0;
        __syncthreads();
        sh[t] += v;
        __syncthreads();
    }
    int excl = sh[t] - s;
#pragma unroll
    for (int i = 0; i < PER; i++) {
        int idx = base + i;
        if (idx < NN) { g_off[idx] = excl + loc[i]; g_cur[idx] = excl + loc[i]; }
    }
    if (t == 1023) g_off[NN] = sh[1023];
}

// ---------------- geometry + scatter into CSR order ----------------
__global__ void k_fill(const int* __restrict__ ei, const float* __restrict__ pos) {
    int e = blockIdx.x * 256 + threadIdx.x;
    if (e >= NE) return;
    int s = ei[e], d = ei[NE + e];
    float rx = pos[d * 3 + 0] - pos[s * 3 + 0];
    float ry = pos[d * 3 + 1] - pos[s * 3 + 1];
    float rz = pos[d * 3 + 2] - pos[s * 3 + 2];
    float nrm = sqrtf(rx * rx + ry * ry + rz * rz);
    float inv = 1.0f / (nrm + 1e-9f);
    int p = atomicAdd(&g_cur[d], 1);
    g_srcs[p] = s;
    ((float4*)g_US)[p] = make_float4(rx * inv, ry * inv, rz * inv, 0.f);
}

// ---------------- layer-0 fused gather+update: warp per (node, c) ----------------
// h0 const across nodes, h1=h2=0 => A_c = accvec_c (outer) moments_c; messages
// factorize: M_c[d][j] = (f_c * av_c)[j] * mom_c[d], so the channel mix reduces to
// one GEMV t[ch] = sum_j mw[ch,j] g_c[j], scaled by warp-uniform moments.
__global__ __launch_bounds__(256) void k_upd0(const float* __restrict__ ws_w,
                                              const float* __restrict__ cwg,
                                              const float* __restrict__ mwg) {
    __shared__ float FS[8][32];
    __shared__ float HS[8][32];
    int warp = threadIdx.x >> 5, lane = threadIdx.x & 31;
    int wg = blockIdx.x * 8 + warp;
    int c = wg / NN;
    int node = wg - c * NN;
    int beg = g_off[node], end = g_off[node + 1];
    float cnt = (float)(end - beg);
    float av0 = g_accvec[lane];
    float s0 = av0 * cnt;                         // A0 per channel
    float s0q = s0 * s0;
    const float* ws = ws_w + lane;                // l = 0
    size_t wbase = ((size_t)c * NN + node) * 1024 + (size_t)lane * 32;

    float mr[32];
#pragma unroll
    for (int q = 0; q < 8; q++) {
        float4 w = ((const float4*)(mwg + wbase))[q];
        mr[4 * q] = w.x; mr[4 * q + 1] = w.y; mr[4 * q + 2] = w.z; mr[4 * q + 3] = w.w;
    }

    if (c == 0) {
        float cr[32];
#pragma unroll
        for (int q = 0; q < 8; q++) {
            float4 v = ((const float4*)(cwg + wbase))[q];
            cr[4 * q] = v.x; cr[4 * q + 1] = v.y; cr[4 * q + 2] = v.z; cr[4 * q + 3] = v.w;
        }
        float f0 = ws[0] + ws[32] * s0 + ws[64] * s0q;
        FS[warp][lane] = f0 * s0;                 // M0
        HS[warp][lane] = g_H0[node * 32 + lane];
        __syncwarp();
        float o = 0.f;
#pragma unroll
        for (int j = 0; j < 32; j++) o += cr[j] * HS[warp][j] + mr[j] * FS[warp][j];
        __syncwarp();
        g_H0[node * 32 + lane] = o;
    } else if (c == 1) {
        // first moment of u over incident edges
        float su0 = 0, su1 = 0, su2 = 0;
        for (int idx = beg + lane; idx < end; idx += 32) {
            float4 u = ((const float4*)g_US)[idx];
            su0 += u.x; su1 += u.y; su2 += u.z;
        }
#pragma unroll
        for (int off = 16; off; off >>= 1) {
            su0 += __shfl_xor_sync(~0u, su0, off);
            su1 += __shfl_xor_sync(~0u, su1, off);
            su2 += __shfl_xor_sync(~0u, su2, off);
        }
        float f1 = ws[96] + ws[128] * s0 + ws[160] * s0q;
        FS[warp][lane] = f1 * g_accvec[32 + lane];
        __syncwarp();
        float t = 0.f;
#pragma unroll
        for (int j = 0; j < 32; j++) t += mr[j] * FS[warp][j];
        __syncwarp();
        float* op = g_H1 + node * 96;
        op[lane] = su0 * t; op[32 + lane] = su1 * t; op[64 + lane] = su2 * t;
    } else {
        // second moment of u
        float s00 = 0, s01 = 0, s02 = 0, s11 = 0, s12 = 0, s22 = 0;
        for (int idx = beg + lane; idx < end; idx += 32) {
            float4 u = ((const float4*)g_US)[idx];
            s00 += u.x * u.x; s01 += u.x * u.y; s02 += u.x * u.z;
            s11 += u.y * u.y; s12 += u.y * u.z; s22 += u.z * u.z;
        }
#pragma unroll
        for (int off = 16; off; off >>= 1) {
            s00 += __shfl_xor_sync(~0u, s00, off);
            s01 += __shfl_xor_sync(~0u, s01, off);
            s02 += __shfl_xor_sync(~0u, s02, off);
            s11 += __shfl_xor_sync(~0u, s11, off);
            s12 += __shfl_xor_sync(~0u, s12, off);
            s22 += __shfl_xor_sync(~0u, s22, off);
        }
        float f2 = ws[192] + ws[224] * s0 + ws[256] * s0q;
        FS[warp][lane] = f2 * g_accvec[64 + lane];
        __syncwarp();
        float t = 0.f;
#pragma unroll
        for (int j = 0; j < 32; j++) t += mr[j] * FS[warp][j];
        __syncwarp();
        float* op = g_H2 + node * 288;
        op[lane]             = s00 * t; op[32 + lane]  = s01 * t; op[64 + lane]  = s02 * t;
        op[96 + lane]        = s01 * t; op[128 + lane] = s11 * t; op[160 + lane] = s12 * t;
        op[192 + lane]       = s02 * t; op[224 + lane] = s12 * t; op[256 + lane] = s22 * t;
    }
}

// ---------------- layer-1 edge kernel: fused S-build + (96x96)@(96xE) GEMM -------
// 256 threads / 128 CSR slots; thread tile 12k x 4e (mg in [0,8), ng in [0,32)).
// Per j: 6 LDS.64 (W pairs) + 4 LDS.32 (S) vs 24 fma2 -> FMA-pipe bound.
// Dyn smem: W 9216 + S 3*128*33 = 21888 floats = 87552 B (2 blocks/SM).
__global__ __launch_bounds__(256) void k_edge(const float* __restrict__ W_ab) {
    extern __shared__ float sm[];
    float* Wt = sm;            // [a*3072 + j*96 + k], thread owns k in [mg*12, mg*12+12)
    float* Ss = sm + 9216;     // [a*4224 + e_loc*33 + j]
    int tid = threadIdx.x;
    int warp = tid >> 5, lane = tid & 31;
    int mg = tid & 7;
    int ng = tid >> 3;
    int e_base = blockIdx.x * 128;

    // ---- phase 1: s_a for all 3 ranks (8 warps x 16 slots, lane = channel j)
#pragma unroll 4
    for (int t2 = 0; t2 < 16; t2++) {
        int e_loc = warp * 16 + t2;
        int idx = e_base + e_loc;
        int src = g_srcs[idx];
        float4 u = ((const float4*)g_US)[idx];
        float s0 = g_H0[src * 32 + lane];
        const float* h1 = g_H1 + src * 96;
        float s1 = h1[lane] * u.x + h1[32 + lane] * u.y + h1[64 + lane] * u.z;
        const float* h2 = g_H2 + src * 288;
        float s2 = u.x * (h2[lane] * u.x + h2[32 + lane] * u.y + h2[64 + lane] * u.z)
                 + u.y * (h2[96 + lane] * u.x + h2[128 + lane] * u.y + h2[160 + lane] * u.z)
                 + u.z * (h2[192 + lane] * u.x + h2[224 + lane] * u.y + h2[256 + lane] * u.z);
        Ss[e_loc * 33 + lane] = s0;
        Ss[4224 + e_loc * 33 + lane] = s1;
        Ss[8448 + e_loc * 33 + lane] = s2;
    }
    // ---- load all W (l=1): Wt[a*3072 + j*96 + k] = W[l1, k>>5, a, k&31, j]
    for (int t = tid; t < 9216; t += 256) {
        int a = t / 3072, rem = t - a * 3072;
        int j = rem / 96, k = rem - j * 96;
        Wt[t] = W_ab[((3 + (k >> 5)) * 3 + a) * 1024 + (k & 31) * 32 + j];
    }
    __syncthreads();

    unsigned long long acc2[6][4];
#pragma unroll
    for (int p = 0; p < 6; p++)
#pragma unroll
        for (int ee = 0; ee < 4; ee++) acc2[p][ee] = 0ull;

#pragma unroll
    for (int a = 0; a < 3; a++) {
        const float* Wa = Wt + a * 3072;
        const float* Sa = Ss + a * 4224;
#pragma unroll 8
        for (int j = 0; j < 32; j++) {
            const unsigned long long* wp =
                (const unsigned long long*)&Wa[j * 96 + mg * 12];
            unsigned long long w0 = wp[0], w1 = wp[1], w2 = wp[2];
            unsigned long long w3 = wp[3], w4 = wp[4], w5 = wp[5];
            unsigned long long s2v[4];
#pragma unroll
            for (int ee = 0; ee < 4; ee++) {
                float s = Sa[(ng + 32 * ee) * 33 + j];
                s2v[ee] = pack2(s, s);
            }
#pragma unroll
            for (int ee = 0; ee < 4; ee++) {
                acc2[0][ee] = fma2(w0, s2v[ee], acc2[0][ee]);
                acc2[1][ee] = fma2(w1, s2v[ee], acc2[1][ee]);
                acc2[2][ee] = fma2(w2, s2v[ee], acc2[2][ee]);
                acc2[3][ee] = fma2(w3, s2v[ee], acc2[3][ee]);
                acc2[4][ee] = fma2(w4, s2v[ee], acc2[4][ee]);
                acc2[5][ee] = fma2(w5, s2v[ee], acc2[5][ee]);
            }
        }
    }
    // ---- store ACC at CSR position: thread owns 12 contiguous k -> 6 float2 stores
#pragma unroll
    for (int ee = 0; ee < 4; ee++) {
        int idx = e_base + ng + 32 * ee;
        float2* op = (float2*)(g_ACC + (size_t)idx * 96 + mg * 12);
#pragma unroll
        for (int p = 0; p < 6; p++) {
            float lo, hi;
            unpack2(acc2[p][ee], lo, hi);
            op[p] = make_float2(lo, hi);
        }
    }
}

// ---------------- layer-1 gather: stream sorted ACC/U -> messages ----------------
__global__ __launch_bounds__(256) void k_gather1(const float* __restrict__ ws_w) {
    int warp = threadIdx.x >> 5, lane = threadIdx.x & 31;
    int node = blockIdx.x * 8 + warp;
    int beg = g_off[node], end = g_off[node + 1];

    float A0 = 0.f, A1[3] = {0.f, 0.f, 0.f};
    float A2[9] = {0.f, 0.f, 0.f, 0.f, 0.f, 0.f, 0.f, 0.f, 0.f};
    int idx = beg;
    for (; idx + 2 <= end; idx += 2) {
        float4 ua = ((const float4*)g_US)[idx];
        float4 ub = ((const float4*)g_US)[idx + 1];
        const float* ap = g_ACC + (size_t)idx * 96 + lane;
        float a0a = ap[0], a1a = ap[32], a2a = ap[64];
        float a0b = ap[96], a1b = ap[128], a2b = ap[160];
        A0 += a0a + a0b;
        A1[0] += a1a * ua.x + a1b * ub.x;
        A1[1] += a1a * ua.y + a1b * ub.y;
        A1[2] += a1a * ua.z + a1b * ub.z;
        float c0 = a2a * ua.x, c1 = a2a * ua.y, c2 = a2a * ua.z;
        float d0 = a2b * ub.x, d1 = a2b * ub.y, d2 = a2b * ub.z;
        A2[0] += c0 * ua.x + d0 * ub.x; A2[1] += c0 * ua.y + d0 * ub.y; A2[2] += c0 * ua.z + d0 * ub.z;
        A2[3] += c1 * ua.x + d1 * ub.x; A2[4] += c1 * ua.y + d1 * ub.y; A2[5] += c1 * ua.z + d1 * ub.z;
        A2[6] += c2 * ua.x + d2 * ub.x; A2[7] += c2 * ua.y + d2 * ub.y; A2[8] += c2 * ua.z + d2 * ub.z;
    }
    if (idx < end) {
        float4 u = ((const float4*)g_US)[idx];
        const float* ap = g_ACC + (size_t)idx * 96 + lane;
        float a0 = ap[0], a1 = ap[32], a2 = ap[64];
        A0 += a0;
        A1[0] += a1 * u.x; A1[1] += a1 * u.y; A1[2] += a1 * u.z;
        float b0 = a2 * u.x, b1 = a2 * u.y, b2 = a2 * u.z;
        A2[0] += b0 * u.x; A2[1] += b0 * u.y; A2[2] += b0 * u.z;
        A2[3] += b1 * u.x; A2[4] += b1 * u.y; A2[5] += b1 * u.z;
        A2[6] += b2 * u.x; A2[7] += b2 * u.y; A2[8] += b2 * u.z;
    }

    const float* ws = ws_w + 288 + lane;  // l=1
    float s0 = A0;
    float f0 = ws[0]   + ws[32]  * s0 + ws[64]  * s0 * s0;
    float f1 = ws[96]  + ws[128] * s0 + ws[160] * s0 * s0;
    float f2 = ws[192] + ws[224] * s0 + ws[256] * s0 * s0;

    float* Mp = g_M + node * 416;
    Mp[lane] = f0 * A0;
#pragma unroll
    for (int d = 0; d < 3; d++) Mp[32 + d * 32 + lane] = f1 * A1[d];
#pragma unroll
    for (int d = 0; d < 9; d++) Mp[128 + d * 32 + lane] = f2 * A2[d];
}

// ---------------- layer-1 update: warp per (node, c); writes output ----------------
__global__ __launch_bounds__(256) void k_upd1(const float* __restrict__ cwg,
                                              const float* __restrict__ mwg,
                                              float* __restrict__ out) {
    __shared__ float XS[8][288];
    __shared__ float HS[8][288];
    int warp = threadIdx.x >> 5, lane = threadIdx.x & 31;
    int wg = blockIdx.x * 8 + warp;
    int c = wg / NN;
    int node = wg - c * NN;
    float* xs = XS[warp];
    float* hs = HS[warp];
    const float* Mp = g_M + node * 416;
    size_t wbase = (((size_t)3 + c) * NN + node) * 1024 + (size_t)lane * 32;

    float mr[32], cr[32];
#pragma unroll
    for (int q = 0; q < 8; q++) {
        float4 w = ((const float4*)(mwg + wbase))[q];
        mr[4 * q] = w.x; mr[4 * q + 1] = w.y; mr[4 * q + 2] = w.z; mr[4 * q + 3] = w.w;
        float4 v = ((const float4*)(cwg + wbase))[q];
        cr[4 * q] = v.x; cr[4 * q + 1] = v.y; cr[4 * q + 2] = v.z; cr[4 * q + 3] = v.w;
    }

    if (c == 0) {
        xs[lane] = Mp[lane];
        hs[lane] = g_H0[node * 32 + lane];
        __syncwarp();
        float o = 0.f;
#pragma unroll
        for (int j = 0; j < 32; j++) o += cr[j] * hs[j] + mr[j] * xs[j];
        __syncwarp();
        out[(node * 32 + lane) * 13 + 0] = o;
    } else if (c == 1) {
        const float* hp = g_H1 + node * 96;
#pragma unroll
        for (int q = 0; q < 3; q++) {
            xs[q * 32 + lane] = Mp[32 + q * 32 + lane];
            hs[q * 32 + lane] = hp[q * 32 + lane];
        }
        __syncwarp();
        float o0 = 0.f, o1 = 0.f, o2 = 0.f;
#pragma unroll
        for (int j = 0; j < 32; j++) {
            float w2 = mr[j], w1 = cr[j];
            o0 += w1 * hs[j]      + w2 * xs[j];
            o1 += w1 * hs[32 + j] + w2 * xs[32 + j];
            o2 += w1 * hs[64 + j] + w2 * xs[64 + j];
        }
        __syncwarp();
        float* op = out + (node * 32 + lane) * 13 + 1;
        op[0] = o0; op[1] = o1; op[2] = o2;
    } else {
        const float* hp = g_H2 + node * 288;
#pragma unroll
        for (int q = 0; q < 9; q++) {
            xs[q * 32 + lane] = Mp[128 + q * 32 + lane];
            hs[q * 32 + lane] = hp[q * 32 + lane];
        }
        __syncwarp();
        float o[9];
#pragma unroll
        for (int d = 0; d < 9; d++) o[d] = 0.f;
#pragma unroll
        for (int j = 0; j < 32; j++) {
            float w2 = mr[j], w1 = cr[j];
#pragma unroll
            for (int d = 0; d < 9; d++) o[d] += w1 * hs[d * 32 + j] + w2 * xs[d * 32 + j];
        }
        __syncwarp();
        float* op = out + (node * 32 + lane) * 13 + 4;
#pragma unroll
        for (int d = 0; d < 9; d++) op[d] = o[d];
    }
}

extern "C" void kernel_launch(void* const* d_in, const int* in_sizes, int n_in,
                              void* d_out, int out_size) {
    (void)in_sizes; (void)n_in; (void)out_size;
    const float* pos   = (const float*)d_in[0];
    const int*   ei    = (const int*)d_in[1];
    const int*   atoms = (const int*)d_in[2];
    const float* emb   = (const float*)d_in[3];
    const float* W_ab  = (const float*)d_in[4];
    const float* ws_w  = (const float*)d_in[5];
    const float* cw    = (const float*)d_in[6];
    const float* mw    = (const float*)d_in[7];
    float* out = (float*)d_out;

    const int EDGE_SMEM = (9216 + 3 * 128 * 33) * 4;   // 87552 B
    cudaFuncSetAttribute(k_edge, cudaFuncAttributeMaxDynamicSharedMemorySize, EDGE_SMEM);

    k_init<<<1250, 256>>>(emb, atoms, W_ab, ei);
    k_scan<<<1, 1024>>>();
    k_fill<<<625, 256>>>(ei, pos);

    // layer 0 (edge phase analytic; gather fused into update)
    k_upd0<<<3 * NN / 8, 256>>>(ws_w, cw, mw);
    // layer 1
    k_edge<<<NE / 128, 256, EDGE_SMEM>>>(W_ab);
    k_gather1<<<NN / 8, 256>>>(ws_w);
    k_upd1<<<3 * NN / 8, 256>>>(cw, mw, out);
}

// round 7
// speedup vs baseline: 1.0991x; 1.0991x over previous
#include <cuda_runtime.h>
#include <math.h>

#define NN 10000
#define NE 160000

// ---------------- scratch (static device globals; no allocation) ----------------
__device__ float g_US[NE * 4];           // sorted unit vectors (float4 per CSR slot)
__device__ int   g_srcs[NE];             // sorted src node per CSR slot
__device__ int   g_cnt[NN];              // INVARIANT: zero at kernel_launch entry/exit
__device__ int   g_off[NN + 1];
__device__ int   g_cur[NN];
__device__ float g_H0[NN * 32];          // (N,C)
__device__ float g_H1[NN * 96];          // (N, d-major: d*32 + ch)
__device__ float g_H2[NN * 288];         // (N, d-major: d*32 + ch)
__device__ float g_ACC[NE * 96];         // per-CSR-slot acc (k index)
__device__ float g_accvec[96];           // layer-0 constant acc vector
__device__ float g_M[NN * 416];          // layer-1 messages

// ---------------- packed f32x2 helpers ----------------
__device__ __forceinline__ unsigned long long pack2(float x, float y) {
    unsigned long long r; asm("mov.b64 %0, {%1,%2};" : "=l"(r) : "f"(x), "f"(y)); return r;
}
__device__ __forceinline__ void unpack2(unsigned long long v, float& x, float& y) {
    asm("mov.b64 {%0,%1}, %2;" : "=f"(x), "=f"(y) : "l"(v));
}
__device__ __forceinline__ unsigned long long fma2(unsigned long long a, unsigned long long b,
                                                   unsigned long long c) {
    unsigned long long d;
    asm("fma.rn.f32x2 %0, %1, %2, %3;" : "=l"(d) : "l"(a), "l"(b), "l"(c));
    return d;
}

// Stage a 32x32 weight matrix (1024 contiguous floats) into shared, coalesced.
// ww layout: row r at ww[r*33 .. r*33+31] (stride 33 => conflict-free STS & LDS).
__device__ __forceinline__ void stage_w(const float* __restrict__ g, float* ww, int lane) {
#pragma unroll
    for (int q = 0; q < 8; q++) {
        float4 v = ((const float4*)g)[q * 32 + lane];   // floats [q*128 + lane*4 ..+3]
        int r = q * 4 + (lane >> 3);
        float* p = ww + r * 33 + (lane & 7) * 4;
        p[0] = v.x; p[1] = v.y; p[2] = v.z; p[3] = v.w;
    }
}
__device__ __forceinline__ void read_row(const float* ww, float* reg, int lane) {
#pragma unroll
    for (int j = 0; j < 32; j++) reg[j] = ww[lane * 33 + j];
}

// ---------------- init: embed atoms, dst histogram, layer-0 accvec ----------------
__global__ void k_init(const float* __restrict__ emb, const int* __restrict__ atoms,
                       const float* __restrict__ W_ab, const int* __restrict__ ei) {
    int t = blockIdx.x * 256 + threadIdx.x;
    if (t < NN * 32) g_H0[t] = emb[atoms[t >> 5] * 32 + (t & 31)];
    if (t < NE)      atomicAdd(&g_cnt[ei[NE + t]], 1);
    if (t < 96) {
        int c = t >> 5, j = t & 31;
        const float* wp = W_ab + (c * 3) * 1024 + j * 32;
        float s = 0.f;
#pragma unroll
        for (int k = 0; k < 32; k++) s += wp[k] * emb[k];
        g_accvec[t] = s;
    }
}

// ---------------- single-block exclusive scan; re-zeroes g_cnt ----------------
__global__ void k_scan() {
    __shared__ int sh[1024];
    int t = threadIdx.x;
    const int PER = 10;
    int base = t * PER;
    int loc[PER];
    int s = 0;
#pragma unroll
    for (int i = 0; i < PER; i++) {
        int idx = base + i;
        int v = (idx < NN) ? g_cnt[idx] : 0;
        if (idx < NN) g_cnt[idx] = 0;
        loc[i] = s;
        s += v;
    }
    sh[t] = s;
    __syncthreads();
    for (int off = 1; off < 1024; off <<= 1) {
        int v = (t >= off) ? sh[t - off] : 0;
        __syncthreads();
        sh[t] += v;
        __syncthreads();
    }
    int excl = sh[t] - s;
#pragma unroll
    for (int i = 0; i < PER; i++) {
        int idx = base + i;
        if (idx < NN) { g_off[idx] = excl + loc[i]; g_cur[idx] = excl + loc[i]; }
    }
    if (t == 1023) g_off[NN] = sh[1023];
}

// ---------------- geometry + scatter into CSR order ----------------
__global__ void k_fill(const int* __restrict__ ei, const float* __restrict__ pos) {
    int e = blockIdx.x * 256 + threadIdx.x;
    if (e >= NE) return;
    int s = ei[e], d = ei[NE + e];
    float rx = pos[d * 3 + 0] - pos[s * 3 + 0];
    float ry = pos[d * 3 + 1] - pos[s * 3 + 1];
    float rz = pos[d * 3 + 2] - pos[s * 3 + 2];
    float nrm = sqrtf(rx * rx + ry * ry + rz * rz);
    float inv = 1.0f / (nrm + 1e-9f);
    int p = atomicAdd(&g_cur[d], 1);
    g_srcs[p] = s;
    ((float4*)g_US)[p] = make_float4(rx * inv, ry * inv, rz * inv, 0.f);
}

// ---------------- layer-0 fused gather+update: warp per (node, c) ----------------
// dyn smem: ww1[8][1056] + ww2[8][1056] = 67584 B
__global__ __launch_bounds__(256) void k_upd0(const float* __restrict__ ws_w,
                                              const float* __restrict__ cwg,
                                              const float* __restrict__ mwg) {
    extern __shared__ float dsm[];
    __shared__ float FS[8][32];
    __shared__ float HS[8][32];
    int warp = threadIdx.x >> 5, lane = threadIdx.x & 31;
    float* ww1 = dsm + warp * 1056;
    float* ww2 = dsm + 8448 + warp * 1056;
    int wg = blockIdx.x * 8 + warp;
    int c = wg / NN;
    int node = wg - c * NN;
    int beg = g_off[node], end = g_off[node + 1];
    float cnt = (float)(end - beg);
    float av0 = g_accvec[lane];
    float s0 = av0 * cnt;
    float s0q = s0 * s0;
    const float* ws = ws_w + lane;                // l = 0
    size_t mbase = ((size_t)c * NN + node) * 1024;

    stage_w(mwg + mbase, ww1, lane);

    if (c == 0) {
        stage_w(cwg + mbase, ww2, lane);
        __syncwarp();
        float mr[32], cr[32];
        read_row(ww1, mr, lane);
        read_row(ww2, cr, lane);
        float f0 = ws[0] + ws[32] * s0 + ws[64] * s0q;
        FS[warp][lane] = f0 * s0;                 // M0
        HS[warp][lane] = g_H0[node * 32 + lane];
        __syncwarp();
        float o = 0.f;
#pragma unroll
        for (int j = 0; j < 32; j++) o += cr[j] * HS[warp][j] + mr[j] * FS[warp][j];
        __syncwarp();
        g_H0[node * 32 + lane] = o;
    } else if (c == 1) {
        float su0 = 0, su1 = 0, su2 = 0;
        for (int idx = beg + lane; idx < end; idx += 32) {
            float4 u = ((const float4*)g_US)[idx];
            su0 += u.x; su1 += u.y; su2 += u.z;
        }
#pragma unroll
        for (int off = 16; off; off >>= 1) {
            su0 += __shfl_xor_sync(~0u, su0, off);
            su1 += __shfl_xor_sync(~0u, su1, off);
            su2 += __shfl_xor_sync(~0u, su2, off);
        }
        __syncwarp();
        float mr[32];
        read_row(ww1, mr, lane);
        float f1 = ws[96] + ws[128] * s0 + ws[160] * s0q;
        FS[warp][lane] = f1 * g_accvec[32 + lane];
        __syncwarp();
        float t = 0.f;
#pragma unroll
        for (int j = 0; j < 32; j++) t += mr[j] * FS[warp][j];
        __syncwarp();
        float* op = g_H1 + node * 96;
        op[lane] = su0 * t; op[32 + lane] = su1 * t; op[64 + lane] = su2 * t;
    } else {
        float s00 = 0, s01 = 0, s02 = 0, s11 = 0, s12 = 0, s22 = 0;
        for (int idx = beg + lane; idx < end; idx += 32) {
            float4 u = ((const float4*)g_US)[idx];
            s00 += u.x * u.x; s01 += u.x * u.y; s02 += u.x * u.z;
            s11 += u.y * u.y; s12 += u.y * u.z; s22 += u.z * u.z;
        }
#pragma unroll
        for (int off = 16; off; off >>= 1) {
            s00 += __shfl_xor_sync(~0u, s00, off);
            s01 += __shfl_xor_sync(~0u, s01, off);
            s02 += __shfl_xor_sync(~0u, s02, off);
            s11 += __shfl_xor_sync(~0u, s11, off);
            s12 += __shfl_xor_sync(~0u, s12, off);
            s22 += __shfl_xor_sync(~0u, s22, off);
        }
        __syncwarp();
        float mr[32];
        read_row(ww1, mr, lane);
        float f2 = ws[192] + ws[224] * s0 + ws[256] * s0q;
        FS[warp][lane] = f2 * g_accvec[64 + lane];
        __syncwarp();
        float t = 0.f;
#pragma unroll
        for (int j = 0; j < 32; j++) t += mr[j] * FS[warp][j];
        __syncwarp();
        float* op = g_H2 + node * 288;
        op[lane]       = s00 * t; op[32 + lane]  = s01 * t; op[64 + lane]  = s02 * t;
        op[96 + lane]  = s01 * t; op[128 + lane] = s11 * t; op[160 + lane] = s12 * t;
        op[192 + lane] = s02 * t; op[224 + lane] = s12 * t; op[256 + lane] = s22 * t;
    }
}

// ---------------- layer-1 edge kernel: fused S-build + (96x96)@(96xE) GEMM -------
// 256 threads / 128 CSR slots; thread tile 6k x 8e (mg in [0,16), ng in [0,16)).
// Permuted W layout: Wt[a*3072 + j*96 + mg*6 + kk] with k = mg + 16*kk -> LDS.64
// pairs, conflict-free. Dyn smem: 9216 + 3*128*33 = 21888 floats = 87552 B.
__global__ __launch_bounds__(256) void k_edge(const float* __restrict__ W_ab) {
    extern __shared__ float sm[];
    float* Wt = sm;
    float* Ss = sm + 9216;     // [a*4224 + e_loc*33 + j]
    int tid = threadIdx.x;
    int warp = tid >> 5, lane = tid & 31;
    int mg = tid & 15;
    int ng = tid >> 4;
    int e_base = blockIdx.x * 128;

    // ---- phase 1: s_a for all 3 ranks (8 warps x 16 slots, lane = channel j)
#pragma unroll 4
    for (int t2 = 0; t2 < 16; t2++) {
        int e_loc = warp * 16 + t2;
        int idx = e_base + e_loc;
        int src = g_srcs[idx];
        float4 u = ((const float4*)g_US)[idx];
        float s0 = g_H0[src * 32 + lane];
        const float* h1 = g_H1 + src * 96;
        float s1 = h1[lane] * u.x + h1[32 + lane] * u.y + h1[64 + lane] * u.z;
        const float* h2 = g_H2 + src * 288;
        float s2 = u.x * (h2[lane] * u.x + h2[32 + lane] * u.y + h2[64 + lane] * u.z)
                 + u.y * (h2[96 + lane] * u.x + h2[128 + lane] * u.y + h2[160 + lane] * u.z)
                 + u.z * (h2[192 + lane] * u.x + h2[224 + lane] * u.y + h2[256 + lane] * u.z);
        Ss[e_loc * 33 + lane] = s0;
        Ss[4224 + e_loc * 33 + lane] = s1;
        Ss[8448 + e_loc * 33 + lane] = s2;
    }
    // ---- load all W (l=1), permuted for paired LDS.64 access
    for (int t = tid; t < 9216; t += 256) {
        int a = t / 3072, rem = t - a * 3072;
        int j = rem / 96, r = rem - j * 96;
        int mgi = r / 6, kki = r - mgi * 6;
        int k = mgi + 16 * kki;
        Wt[t] = W_ab[((3 + (k >> 5)) * 3 + a) * 1024 + (k & 31) * 32 + j];
    }
    __syncthreads();

    unsigned long long acc2[3][8];
#pragma unroll
    for (int p = 0; p < 3; p++)
#pragma unroll
        for (int ee = 0; ee < 8; ee++) acc2[p][ee] = 0ull;

#pragma unroll
    for (int a = 0; a < 3; a++) {
        const float* Wa = Wt + a * 3072;
        const float* Sa = Ss + a * 4224;
#pragma unroll 8
        for (int j = 0; j < 32; j++) {
            const unsigned long long* wp =
                (const unsigned long long*)&Wa[j * 96 + mg * 6];
            unsigned long long w0 = wp[0], w1 = wp[1], w2 = wp[2];
            unsigned long long s2v[8];
#pragma unroll
            for (int ee = 0; ee < 8; ee++) {
                float s = Sa[(ng + 16 * ee) * 33 + j];
                s2v[ee] = pack2(s, s);
            }
#pragma unroll
            for (int ee = 0; ee < 8; ee++) {
                acc2[0][ee] = fma2(w0, s2v[ee], acc2[0][ee]);
                acc2[1][ee] = fma2(w1, s2v[ee], acc2[1][ee]);
                acc2[2][ee] = fma2(w2, s2v[ee], acc2[2][ee]);
            }
        }
    }
    // ---- store ACC at CSR position (k-pairs 16 apart; half-warp 64B chunks)
#pragma unroll
    for (int ee = 0; ee < 8; ee++) {
        int idx = e_base + ng + 16 * ee;
        float* op = g_ACC + (size_t)idx * 96 + mg;
#pragma unroll
        for (int p = 0; p < 3; p++) {
            float lo, hi;
            unpack2(acc2[p][ee], lo, hi);
            op[16 * (2 * p)]     = lo;
            op[16 * (2 * p + 1)] = hi;
        }
    }
}

// ---------------- layer-1 gather: stream sorted ACC/U -> messages ----------------
__global__ __launch_bounds__(256) void k_gather1(const float* __restrict__ ws_w) {
    int warp = threadIdx.x >> 5, lane = threadIdx.x & 31;
    int node = blockIdx.x * 8 + warp;
    int beg = g_off[node], end = g_off[node + 1];

    float A0 = 0.f, A1[3] = {0.f, 0.f, 0.f};
    float A2[9] = {0.f, 0.f, 0.f, 0.f, 0.f, 0.f, 0.f, 0.f, 0.f};
    int idx = beg;
    for (; idx + 2 <= end; idx += 2) {
        float4 ua = ((const float4*)g_US)[idx];
        float4 ub = ((const float4*)g_US)[idx + 1];
        const float* ap = g_ACC + (size_t)idx * 96 + lane;
        float a0a = ap[0], a1a = ap[32], a2a = ap[64];
        float a0b = ap[96], a1b = ap[128], a2b = ap[160];
        A0 += a0a + a0b;
        A1[0] += a1a * ua.x + a1b * ub.x;
        A1[1] += a1a * ua.y + a1b * ub.y;
        A1[2] += a1a * ua.z + a1b * ub.z;
        float c0 = a2a * ua.x, c1 = a2a * ua.y, c2 = a2a * ua.z;
        float d0 = a2b * ub.x, d1 = a2b * ub.y, d2 = a2b * ub.z;
        A2[0] += c0 * ua.x + d0 * ub.x; A2[1] += c0 * ua.y + d0 * ub.y; A2[2] += c0 * ua.z + d0 * ub.z;
        A2[3] += c1 * ua.x + d1 * ub.x; A2[4] += c1 * ua.y + d1 * ub.y; A2[5] += c1 * ua.z + d1 * ub.z;
        A2[6] += c2 * ua.x + d2 * ub.x; A2[7] += c2 * ua.y + d2 * ub.y; A2[8] += c2 * ua.z + d2 * ub.z;
    }
    if (idx < end) {
        float4 u = ((const float4*)g_US)[idx];
        const float* ap = g_ACC + (size_t)idx * 96 + lane;
        float a0 = ap[0], a1 = ap[32], a2 = ap[64];
        A0 += a0;
        A1[0] += a1 * u.x; A1[1] += a1 * u.y; A1[2] += a1 * u.z;
        float b0 = a2 * u.x, b1 = a2 * u.y, b2 = a2 * u.z;
        A2[0] += b0 * u.x; A2[1] += b0 * u.y; A2[2] += b0 * u.z;
        A2[3] += b1 * u.x; A2[4] += b1 * u.y; A2[5] += b1 * u.z;
        A2[6] += b2 * u.x; A2[7] += b2 * u.y; A2[8] += b2 * u.z;
    }

    const float* ws = ws_w + 288 + lane;  // l=1
    float s0 = A0;
    float f0 = ws[0]   + ws[32]  * s0 + ws[64]  * s0 * s0;
    float f1 = ws[96]  + ws[128] * s0 + ws[160] * s0 * s0;
    float f2 = ws[192] + ws[224] * s0 + ws[256] * s0 * s0;

    float* Mp = g_M + node * 416;
    Mp[lane] = f0 * A0;
#pragma unroll
    for (int d = 0; d < 3; d++) Mp[32 + d * 32 + lane] = f1 * A1[d];
#pragma unroll
    for (int d = 0; d < 9; d++) Mp[128 + d * 32 + lane] = f2 * A2[d];
}

// ---------------- layer-1 update: warp per (node, c); writes output ----------------
// dyn smem: ww1[8][1056] + ww2[8][1056] = 67584 B (+ static XS/HS 18432 B)
__global__ __launch_bounds__(256) void k_upd1(const float* __restrict__ cwg,
                                              const float* __restrict__ mwg,
                                              float* __restrict__ out) {
    extern __shared__ float dsm[];
    __shared__ float XS[8][288];
    __shared__ float HS[8][288];
    int warp = threadIdx.x >> 5, lane = threadIdx.x & 31;
    float* ww1 = dsm + warp * 1056;
    float* ww2 = dsm + 8448 + warp * 1056;
    int wg = blockIdx.x * 8 + warp;
    int c = wg / NN;
    int node = wg - c * NN;
    float* xs = XS[warp];
    float* hs = HS[warp];
    const float* Mp = g_M + node * 416;
    size_t mbase = (((size_t)3 + c) * NN + node) * 1024;

    stage_w(cwg + mbase, ww1, lane);
    stage_w(mwg + mbase, ww2, lane);
    __syncwarp();
    float cr[32], mr[32];
    read_row(ww1, cr, lane);
    read_row(ww2, mr, lane);

    if (c == 0) {
        xs[lane] = Mp[lane];
        hs[lane] = g_H0[node * 32 + lane];
        __syncwarp();
        float o = 0.f;
#pragma unroll
        for (int j = 0; j < 32; j++) o += cr[j] * hs[j] + mr[j] * xs[j];
        __syncwarp();
        out[(node * 32 + lane) * 13 + 0] = o;
    } else if (c == 1) {
        const float* hp = g_H1 + node * 96;
#pragma unroll
        for (int q = 0; q < 3; q++) {
            xs[q * 32 + lane] = Mp[32 + q * 32 + lane];
            hs[q * 32 + lane] = hp[q * 32 + lane];
        }
        __syncwarp();
        float o0 = 0.f, o1 = 0.f, o2 = 0.f;
#pragma unroll
        for (int j = 0; j < 32; j++) {
            float w2 = mr[j], w1 = cr[j];
            o0 += w1 * hs[j]      + w2 * xs[j];
            o1 += w1 * hs[32 + j] + w2 * xs[32 + j];
            o2 += w1 * hs[64 + j] + w2 * xs[64 + j];
        }
        __syncwarp();
        float* op = out + (node * 32 + lane) * 13 + 1;
        op[0] = o0; op[1] = o1; op[2] = o2;
    } else {
        const float* hp = g_H2 + node * 288;
#pragma unroll
        for (int q = 0; q < 9; q++) {
            xs[q * 32 + lane] = Mp[128 + q * 32 + lane];
            hs[q * 32 + lane] = hp[q * 32 + lane];
        }
        __syncwarp();
        float o[9];
#pragma unroll
        for (int d = 0; d < 9; d++) o[d] = 0.f;
#pragma unroll
        for (int j = 0; j < 32; j++) {
            float w2 = mr[j], w1 = cr[j];
#pragma unroll
            for (int d = 0; d < 9; d++) o[d] += w1 * hs[d * 32 + j] + w2 * xs[d * 32 + j];
        }
        __syncwarp();
        float* op = out + (node * 32 + lane) * 13 + 4;
#pragma unroll
        for (int d = 0; d < 9; d++) op[d] = o[d];
    }
}

extern "C" void kernel_launch(void* const* d_in, const int* in_sizes, int n_in,
                              void* d_out, int out_size) {
    (void)in_sizes; (void)n_in; (void)out_size;
    const float* pos   = (const float*)d_in[0];
    const int*   ei    = (const int*)d_in[1];
    const int*   atoms = (const int*)d_in[2];
    const float* emb   = (const float*)d_in[3];
    const float* W_ab  = (const float*)d_in[4];
    const float* ws_w  = (const float*)d_in[5];
    const float* cw    = (const float*)d_in[6];
    const float* mw    = (const float*)d_in[7];
    float* out = (float*)d_out;

    const int EDGE_SMEM = (9216 + 3 * 128 * 33) * 4;   // 87552 B
    const int UPD_SMEM  = 2 * 8 * 1056 * 4;            // 67584 B
    cudaFuncSetAttribute(k_edge, cudaFuncAttributeMaxDynamicSharedMemorySize, EDGE_SMEM);
    cudaFuncSetAttribute(k_upd0, cudaFuncAttributeMaxDynamicSharedMemorySize, UPD_SMEM);
    cudaFuncSetAttribute(k_upd1, cudaFuncAttributeMaxDynamicSharedMemorySize, UPD_SMEM);

    k_init<<<1250, 256>>>(emb, atoms, W_ab, ei);
    k_scan<<<1, 1024>>>();
    k_fill<<<625, 256>>>(ei, pos);

    // layer 0 (edge phase analytic; gather fused into update)
    k_upd0<<<3 * NN / 8, 256, UPD_SMEM>>>(ws_w, cw, mw);
    // layer 1
    k_edge<<<NE / 128, 256, EDGE_SMEM>>>(W_ab);
    k_gather1<<<NN / 8, 256>>>(ws_w);
    k_upd1<<<3 * NN / 8, 256, UPD_SMEM>>>(cw, mw, out);
}